// round 6
// baseline (speedup 1.0000x reference)
#include <cuda_runtime.h>
#include <cstdint>

// ---------------------------------------------------------------------------
// Problem constants
// ---------------------------------------------------------------------------
#define OUT_DIM 4096
#define IN_DIM  4096
#define M_TOTAL 8192                 // 4 * 2048
#define R_DIM   64
#define KX      (IN_DIM + R_DIM)     // 4160 : K of fused GEMM [x|T] . [W|loraB]^T

// Scratch device globals (allocation-free rule).
// int8 2-split quantization: v = s_row * (128*hi + lo), hi/lo in [-127,127]
__device__ signed char g_Xh[(size_t)M_TOTAL * KX];
__device__ signed char g_Xl[(size_t)M_TOTAL * KX];
__device__ signed char g_Wh[(size_t)OUT_DIM * KX];
__device__ signed char g_Wl[(size_t)OUT_DIM * KX];
__device__ float g_T[(size_t)M_TOTAL * R_DIM];   // 2 * x @ lora_A^T (fp32)
__device__ float g_sx[M_TOTAL];                  // per-row scale of [x|T]
__device__ float g_sw[OUT_DIM];                  // per-row scale of [W|loraB]

__constant__ float c_nf4[16] = {
    -1.0f, -0.6961928009986877f, -0.5250730514526367f, -0.39491748809814453f,
    -0.28444138169288635f, -0.18477343022823334f, -0.09105003625154495f, 0.0f,
    0.07958029955625534f, 0.16093020141124725f, 0.24611230194568634f, 0.33791524171829224f,
    0.44070982933044434f, 0.5626170039176941f, 0.7229568362236023f, 1.0f};

// ---------------------------------------------------------------------------
// Helpers
// ---------------------------------------------------------------------------
__device__ __forceinline__ float rna_tf32(float v) {
    uint32_t r;
    asm("cvt.rna.tf32.f32 %0, %1;" : "=r"(r) : "f"(v));
    return __uint_as_float(r);
}

__device__ __forceinline__ void cp_async16(void* smem_dst, const void* gptr) {
    uint32_t s = (uint32_t)__cvta_generic_to_shared(smem_dst);
    asm volatile("cp.async.cg.shared.global [%0], [%1], 16;" :: "r"(s), "l"(gptr));
}
__device__ __forceinline__ void cp_commit() {
    asm volatile("cp.async.commit_group;" ::: "memory");
}
template <int N>
__device__ __forceinline__ void cp_wait() {
    asm volatile("cp.async.wait_group %0;" :: "n"(N) : "memory");
}

// tf32: D += A(16x8) * B(8x8)
__device__ __forceinline__ void mma_tf32(float* c, const uint32_t* a, const uint32_t* b) {
    asm volatile(
        "mma.sync.aligned.m16n8k8.row.col.f32.tf32.tf32.f32 "
        "{%0,%1,%2,%3}, {%4,%5,%6,%7}, {%8,%9}, {%0,%1,%2,%3};"
        : "+f"(c[0]), "+f"(c[1]), "+f"(c[2]), "+f"(c[3])
        : "r"(a[0]), "r"(a[1]), "r"(a[2]), "r"(a[3]), "r"(b[0]), "r"(b[1]));
}

// s8: D(s32) += A(16x32 s8) * B(32x8 s8)
__device__ __forceinline__ void mma_s8(int* c, const uint32_t* a, const uint32_t* b) {
    asm volatile(
        "mma.sync.aligned.m16n8k32.row.col.s32.s8.s8.s32 "
        "{%0,%1,%2,%3}, {%4,%5,%6,%7}, {%8,%9}, {%0,%1,%2,%3};"
        : "+r"(c[0]), "+r"(c[1]), "+r"(c[2]), "+r"(c[3])
        : "r"(a[0]), "r"(a[1]), "r"(a[2]), "r"(a[3]), "r"(b[0]), "r"(b[1]));
}

// Single extern-shared symbol (char) shared by all kernels; cast per use.
extern __shared__ char smem_raw[];

// ---------------------------------------------------------------------------
// Launch 1: T = 2 * x @ lora_A^T  (tf32 mma, fp32 out; rna applied to frags)
//   BM=128, BN=64(all of R), 256 thr, warps 4x2 (warp 32x32), 3 stages
// ---------------------------------------------------------------------------
__global__ __launch_bounds__(256, 1)
void gemm_T(const float* __restrict__ x, const float* __restrict__ la) {
    constexpr int BM = 128, BN = 64, SA = 36, STAGES = 3;
    constexpr int MT = 2, NT = 4;                 // warp tile 32x32

    float* smem = reinterpret_cast<float*>(smem_raw);
    float* sA = smem;                             // [3][128*36]
    float* sB = smem + STAGES * BM * SA;          // [3][64*36]

    const int tid = threadIdx.x, lane = tid & 31, wid = tid >> 5;
    const int wm = wid & 3, wn = wid >> 2;
    const int lr = lane >> 2, lc = lane & 3;
    const int m0 = blockIdx.x * BM;

    float c[MT][NT][4];
#pragma unroll
    for (int mt = 0; mt < MT; mt++)
#pragma unroll
        for (int nt = 0; nt < NT; nt++)
#pragma unroll
            for (int q = 0; q < 4; q++) c[mt][nt][q] = 0.0f;

    auto load_stage = [&](int s, int kt) {
        const int kk = kt * 32;
        float* dA = sA + s * BM * SA;
        float* dB = sB + s * BN * SA;
#pragma unroll
        for (int i = 0; i < 4; i++) {             // A: 1024 chunks / 256 thr
            int ch = tid + 256 * i, row = ch >> 3, col = (ch & 7) * 4;
            cp_async16(dA + row * SA + col, x + (size_t)(m0 + row) * IN_DIM + kk + col);
        }
#pragma unroll
        for (int i = 0; i < 2; i++) {             // B: 512 chunks
            int ch = tid + 256 * i, row = ch >> 3, col = (ch & 7) * 4;
            cp_async16(dB + row * SA + col, la + (size_t)row * IN_DIM + kk + col);
        }
    };

    auto compute_stage = [&](int s) {
        const uint32_t* ab = reinterpret_cast<const uint32_t*>(sA + s * BM * SA + (wm * 32) * SA);
        const uint32_t* bb = reinterpret_cast<const uint32_t*>(sB + s * BN * SA + (wn * 32) * SA);
#pragma unroll
        for (int ks = 0; ks < 4; ks++) {
            uint32_t af[MT][4], bf[NT][2];
#pragma unroll
            for (int mt = 0; mt < MT; mt++) {
                const uint32_t* p = ab + (mt * 16 + lr) * SA + ks * 8 + lc;
                af[mt][0] = p[0]; af[mt][1] = p[8 * SA];
                af[mt][2] = p[4]; af[mt][3] = p[8 * SA + 4];
#pragma unroll
                for (int j = 0; j < 4; j++)
                    af[mt][j] = __float_as_uint(rna_tf32(__uint_as_float(af[mt][j])));
            }
#pragma unroll
            for (int nt = 0; nt < NT; nt++) {
                const uint32_t* p = bb + (nt * 8 + lr) * SA + ks * 8 + lc;
                bf[nt][0] = p[0]; bf[nt][1] = p[4];
                bf[nt][0] = __float_as_uint(rna_tf32(__uint_as_float(bf[nt][0])));
                bf[nt][1] = __float_as_uint(rna_tf32(__uint_as_float(bf[nt][1])));
            }
#pragma unroll
            for (int mt = 0; mt < MT; mt++)
#pragma unroll
                for (int nt = 0; nt < NT; nt++) mma_tf32(c[mt][nt], af[mt], bf[nt]);
        }
    };

    load_stage(0, 0); cp_commit();
    load_stage(1, 1); cp_commit();
    cp_wait<1>();
    __syncthreads();

    const int nk = IN_DIM / 32;                   // 128
    for (int kt = 0; kt < nk; kt++) {
        int ls = kt + 2;
        if (ls < nk) load_stage(ls % STAGES, ls);
        cp_commit();
        compute_stage(kt % STAGES);
        cp_wait<1>();
        __syncthreads();
    }

#pragma unroll
    for (int mt = 0; mt < MT; mt++) {
        int r0 = m0 + wm * 32 + mt * 16 + lr;
#pragma unroll
        for (int nt = 0; nt < NT; nt++) {
            int cc = wn * 32 + nt * 8 + 2 * lc;
            float2 v0 = make_float2(2.0f * c[mt][nt][0], 2.0f * c[mt][nt][1]);
            float2 v1 = make_float2(2.0f * c[mt][nt][2], 2.0f * c[mt][nt][3]);
            *reinterpret_cast<float2*>(&g_T[(size_t)r0 * R_DIM + cc]) = v0;
            *reinterpret_cast<float2*>(&g_T[(size_t)(r0 + 8) * R_DIM + cc]) = v1;
        }
    }
}

// ---------------------------------------------------------------------------
// Launch 2: fused prep — blocks [0,4096): quantize W rows (NF4 dequant + loraB)
//                        blocks [4096,12288): quantize [x|T] rows
//   128 threads/block, one matrix row per block, 2-split int8.
// ---------------------------------------------------------------------------
__global__ __launch_bounds__(128)
void prep_quant(const float* __restrict__ x,
                const float* __restrict__ lora_B,
                const float* __restrict__ absmax,
                const int* __restrict__ codes) {
    __shared__ float srow[KX];
    __shared__ float sred[4];
    const int b = blockIdx.x, t = threadIdx.x, lane = t & 31, w = t >> 5;

    auto blockmax = [&](float v) -> float {
#pragma unroll
        for (int o = 16; o > 0; o >>= 1)
            v = fmaxf(v, __shfl_xor_sync(0xFFFFFFFFu, v, o));
        if (lane == 0) sred[w] = v;
        __syncthreads();
        float r = fmaxf(fmaxf(sred[0], sred[1]), fmaxf(sred[2], sred[3]));
        return r;
    };

    if (b < OUT_DIM) {
        // ---- W row n = b ----
        float m = 0.0f;
        if (t < 64)
            m = fmaxf(absmax[b * 64 + t], fabsf(lora_B[b * 64 + t]));
        m = blockmax(m);
        float sw = fmaxf(m, 1e-30f) * (1.0f / 16256.0f);
        if (t == 0) g_sw[b] = sw;
        float inv = 1.0f / sw;
        for (int k = t; k < KX; k += 128) {
            float v;
            if (k < IN_DIM)
                v = c_nf4[codes[(size_t)b * IN_DIM + k] & 15] * absmax[b * 64 + (k >> 6)];
            else
                v = lora_B[b * 64 + (k - IN_DIM)];
            float q = v * inv;
            float qh = rintf(q * 0.0078125f);
            float ql = rintf(fmaf(qh, -128.0f, q));
            g_Wh[(size_t)b * KX + k] = (signed char)(int)qh;
            g_Wl[(size_t)b * KX + k] = (signed char)(int)ql;
        }
    } else {
        // ---- X row m = b - 4096 : combined [x row | T row] ----
        const int mr = b - OUT_DIM;
        float mx = 0.0f;
        for (int k = t; k < IN_DIM; k += 128) {
            float v = x[(size_t)mr * IN_DIM + k];
            srow[k] = v;
            mx = fmaxf(mx, fabsf(v));
        }
        if (t < 64) {
            float v = g_T[(size_t)mr * R_DIM + t];
            srow[IN_DIM + t] = v;
            mx = fmaxf(mx, fabsf(v));
        }
        mx = blockmax(mx);
        float sx = fmaxf(mx, 1e-30f) * (1.0f / 16256.0f);
        if (t == 0) g_sx[mr] = sx;
        float inv = 1.0f / sx;
        __syncthreads();
        for (int k = t; k < KX; k += 128) {
            float q = srow[k] * inv;
            float qh = rintf(q * 0.0078125f);
            float ql = rintf(fmaf(qh, -128.0f, q));
            g_Xh[(size_t)mr * KX + k] = (signed char)(int)qh;
            g_Xl[(size_t)mr * KX + k] = (signed char)(int)ql;
        }
    }
}

// ---------------------------------------------------------------------------
// Launch 3: main int8 GEMM with 2-split (3 IMMA per K=32)
//   C[128x128] per CTA, 256 thr, warps 2x4 (warp 64x32), BK=64 int8, 4 stages.
//   smem rows: 64 data + 16 pad = 80 B (conflict-free 32-bit frag loads).
//   out[m][n] = sx[m]*sw[n]*(16384*acc_hh + 128*acc_mid)
// ---------------------------------------------------------------------------
__global__ __launch_bounds__(256, 1)
void gemm_s8(float* __restrict__ out) {
    constexpr int BK = 64, SROW = 80;
    constexpr int MATB = 128 * SROW;              // 10240 B per matrix per stage
    constexpr int STAGE = 4 * MATB;               // Xh, Xl, Wh, Wl
    constexpr int MT = 4, NT = 4;                 // warp tile 64x32
    constexpr int GROUP = 8, NBLK = OUT_DIM / 128;

    char* smem = smem_raw;

    const int tid = threadIdx.x, lane = tid & 31, wid = tid >> 5;
    const int wm = wid & 1, wn = wid >> 1;        // 2 x 4 warps
    const int lr = lane >> 2, lc = lane & 3;

    // grouped rasterization
    const int bid = blockIdx.x;
    const int grp = bid / (GROUP * NBLK);
    const int rem = bid % (GROUP * NBLK);
    const int m0 = (grp * GROUP + rem % GROUP) * 128;
    const int n0 = (rem / GROUP) * 128;

    int chh[MT][NT][4], cmid[MT][NT][4];
#pragma unroll
    for (int mt = 0; mt < MT; mt++)
#pragma unroll
        for (int nt = 0; nt < NT; nt++)
#pragma unroll
            for (int q = 0; q < 4; q++) { chh[mt][nt][q] = 0; cmid[mt][nt][q] = 0; }

    auto load_stage = [&](int s, int kt) {
        const int kk = kt * BK;
        char* base = smem + s * STAGE;
#pragma unroll
        for (int i = 0; i < 2; i++) {
            int ch = tid + 256 * i;               // 512 chunks per matrix
            int row = ch >> 2, c16 = (ch & 3) * 16;
            size_t gx = (size_t)(m0 + row) * KX + kk + c16;
            size_t gw = (size_t)(n0 + row) * KX + kk + c16;
            char* d = base + row * SROW + c16;
            cp_async16(d,            g_Xh + gx);
            cp_async16(d + MATB,     g_Xl + gx);
            cp_async16(d + 2 * MATB, g_Wh + gw);
            cp_async16(d + 3 * MATB, g_Wl + gw);
        }
    };

    auto compute_stage = [&](int s) {
        const char* bx = smem + s * STAGE + (wm * 64) * SROW;
        const char* bw = smem + s * STAGE + 2 * MATB + (wn * 32) * SROW;
#pragma unroll
        for (int ks = 0; ks < 2; ks++) {
            uint32_t axh[MT][4], axl[MT][4], bwh[NT][2], bwl[NT][2];
#pragma unroll
            for (int mt = 0; mt < MT; mt++) {
                const char* p = bx + (mt * 16 + lr) * SROW + ks * 32 + 4 * lc;
                axh[mt][0] = *(const uint32_t*)(p);
                axh[mt][1] = *(const uint32_t*)(p + 8 * SROW);
                axh[mt][2] = *(const uint32_t*)(p + 16);
                axh[mt][3] = *(const uint32_t*)(p + 8 * SROW + 16);
                axl[mt][0] = *(const uint32_t*)(p + MATB);
                axl[mt][1] = *(const uint32_t*)(p + MATB + 8 * SROW);
                axl[mt][2] = *(const uint32_t*)(p + MATB + 16);
                axl[mt][3] = *(const uint32_t*)(p + MATB + 8 * SROW + 16);
            }
#pragma unroll
            for (int nt = 0; nt < NT; nt++) {
                const char* p = bw + (nt * 8 + lr) * SROW + ks * 32 + 4 * lc;
                bwh[nt][0] = *(const uint32_t*)(p);
                bwh[nt][1] = *(const uint32_t*)(p + 16);
                bwl[nt][0] = *(const uint32_t*)(p + MATB);
                bwl[nt][1] = *(const uint32_t*)(p + MATB + 16);
            }
#pragma unroll
            for (int mt = 0; mt < MT; mt++)
#pragma unroll
                for (int nt = 0; nt < NT; nt++) {
                    mma_s8(chh[mt][nt],  axh[mt], bwh[nt]);
                    mma_s8(cmid[mt][nt], axh[mt], bwl[nt]);
                    mma_s8(cmid[mt][nt], axl[mt], bwh[nt]);
                }
        }
    };

    const int nk = KX / BK;                       // 65
    load_stage(0, 0); cp_commit();
    load_stage(1, 1); cp_commit();
    load_stage(2, 2); cp_commit();
    cp_wait<2>();
    __syncthreads();

    for (int kt = 0; kt < nk; kt++) {
        int ls = kt + 3;
        if (ls < nk) load_stage(ls & 3, ls);
        cp_commit();
        compute_stage(kt & 3);
        cp_wait<2>();
        __syncthreads();
    }

    // Epilogue: combine split accumulators with per-row scales
#pragma unroll
    for (int mt = 0; mt < MT; mt++) {
        int r0 = m0 + wm * 64 + mt * 16 + lr;
        float sx0 = g_sx[r0], sx1 = g_sx[r0 + 8];
#pragma unroll
        for (int nt = 0; nt < NT; nt++) {
            int cc = n0 + wn * 32 + nt * 8 + 2 * lc;
            float sw0 = g_sw[cc], sw1 = g_sw[cc + 1];
            float f0 = 16384.0f * (float)chh[mt][nt][0] + 128.0f * (float)cmid[mt][nt][0];
            float f1 = 16384.0f * (float)chh[mt][nt][1] + 128.0f * (float)cmid[mt][nt][1];
            float f2 = 16384.0f * (float)chh[mt][nt][2] + 128.0f * (float)cmid[mt][nt][2];
            float f3 = 16384.0f * (float)chh[mt][nt][3] + 128.0f * (float)cmid[mt][nt][3];
            float2 v0 = make_float2(sx0 * sw0 * f0, sx0 * sw1 * f1);
            float2 v1 = make_float2(sx1 * sw0 * f2, sx1 * sw1 * f3);
            *reinterpret_cast<float2*>(&out[(size_t)r0 * OUT_DIM + cc]) = v0;
            *reinterpret_cast<float2*>(&out[(size_t)(r0 + 8) * OUT_DIM + cc]) = v1;
        }
    }
}

// ---------------------------------------------------------------------------
// Host
// ---------------------------------------------------------------------------
extern "C" void kernel_launch(void* const* d_in, const int* in_sizes, int n_in,
                              void* d_out, int out_size) {
    const float* x      = (const float*)d_in[0];
    const float* lora_A = (const float*)d_in[1];
    const float* lora_B = (const float*)d_in[2];
    const float* absmax = (const float*)d_in[3];
    const int*   codes  = (const int*)d_in[4];
    float* out = (float*)d_out;

    constexpr int SMEM_TG = 3 * (128 + 64) * 36 * 4;   // 82944
    constexpr int SMEM_S8 = 4 * 4 * 128 * 80;          // 163840
    static bool attr_done = false;
    if (!attr_done) {
        cudaFuncSetAttribute((const void*)gemm_T,
                             cudaFuncAttributeMaxDynamicSharedMemorySize, SMEM_TG);
        cudaFuncSetAttribute((const void*)gemm_s8,
                             cudaFuncAttributeMaxDynamicSharedMemorySize, SMEM_S8);
        attr_done = true;
    }

    // 1) T = 2 * x @ lora_A^T  (tf32, fp32 out)
    gemm_T<<<M_TOTAL / 128, 256, SMEM_TG>>>(x, lora_A);

    // 2) quantize W (NF4 dequant + loraB) and [x|T] into int8 2-split
    prep_quant<<<OUT_DIM + M_TOTAL, 128>>>(x, lora_B, absmax, codes);

    // 3) out = [x|T] @ [W|loraB]^T via int8 split MMA
    gemm_s8<<<(M_TOTAL / 128) * (OUT_DIM / 128), 256, SMEM_S8>>>(out);
}

// round 7
// speedup vs baseline: 3.2534x; 3.2534x over previous
#include <cuda_runtime.h>
#include <cstdint>

// ---------------------------------------------------------------------------
// Problem constants
// ---------------------------------------------------------------------------
#define OUT_DIM 4096
#define IN_DIM  4096
#define M_TOTAL 8192                 // 4 * 2048
#define R_DIM   64
#define KX      (IN_DIM + R_DIM)     // 4160 : K of fused GEMM [x|T] . [W|loraB]^T

// Scratch device globals (allocation-free rule).
// K-layout inside every 8-group is PAIR-PERMUTED: position order 0,4,1,5,2,6,3,7
// so tf32 mma fragments (k=lc, k=lc+4) are adjacent -> LDS.64 loads.
__device__ float g_X[(size_t)M_TOTAL * KX];   // [8192][4160] rna(x) | rna(2 x A^T)
__device__ float g_W[(size_t)OUT_DIM * KX];   // [4096][4160] rna(deq W) | rna(lora_B)

__constant__ float c_nf4[16] = {
    -1.0f, -0.6961928009986877f, -0.5250730514526367f, -0.39491748809814453f,
    -0.28444138169288635f, -0.18477343022823334f, -0.09105003625154495f, 0.0f,
    0.07958029955625534f, 0.16093020141124725f, 0.24611230194568634f, 0.33791524171829224f,
    0.44070982933044434f, 0.5626170039176941f, 0.7229568362236023f, 1.0f};

// ---------------------------------------------------------------------------
// Helpers
// ---------------------------------------------------------------------------
__device__ __forceinline__ float rna_tf32(float v) {
    uint32_t r;
    asm("cvt.rna.tf32.f32 %0, %1;" : "=r"(r) : "f"(v));
    return __uint_as_float(r);
}

__device__ __forceinline__ int perm8(int j) {   // 0,4,1,5,2,6,3,7 positions
    return (j < 4) ? 2 * j : 2 * j - 7;
}

__device__ __forceinline__ void cp_async16(void* smem_dst, const void* gptr) {
    uint32_t s = (uint32_t)__cvta_generic_to_shared(smem_dst);
    asm volatile("cp.async.cg.shared.global [%0], [%1], 16;" :: "r"(s), "l"(gptr));
}
__device__ __forceinline__ void cp_commit() {
    asm volatile("cp.async.commit_group;" ::: "memory");
}
template <int N>
__device__ __forceinline__ void cp_wait() {
    asm volatile("cp.async.wait_group %0;" :: "n"(N) : "memory");
}

// tf32: D += A(16x8) * B(8x8)
__device__ __forceinline__ void mma_tf32(float* c, const uint32_t* a, const uint32_t* b) {
    asm volatile(
        "mma.sync.aligned.m16n8k8.row.col.f32.tf32.tf32.f32 "
        "{%0,%1,%2,%3}, {%4,%5,%6,%7}, {%8,%9}, {%0,%1,%2,%3};"
        : "+f"(c[0]), "+f"(c[1]), "+f"(c[2]), "+f"(c[3])
        : "r"(a[0]), "r"(a[1]), "r"(a[2]), "r"(a[3]), "r"(b[0]), "r"(b[1]));
}

extern __shared__ char smem_raw[];

// ---------------------------------------------------------------------------
// Launch 1: T = rna(2 * x @ lora_A^T), written permuted into g_X cols 4096+.
//   Reads raw fp32 x / lora_A; fragments rna-rounded in registers.
//   BM=128, BN=64, 256 thr, warps 4x2 (warp 32x32), 3 stages.
// ---------------------------------------------------------------------------
__global__ __launch_bounds__(256, 1)
void gemm_T(const float* __restrict__ x, const float* __restrict__ la) {
    constexpr int BM = 128, BN = 64, SA = 36, STAGES = 3;
    constexpr int MT = 2, NT = 4;                 // warp tile 32x32

    float* smem = reinterpret_cast<float*>(smem_raw);
    float* sA = smem;
    float* sB = smem + STAGES * BM * SA;

    const int tid = threadIdx.x, lane = tid & 31, wid = tid >> 5;
    const int wm = wid & 3, wn = wid >> 2;
    const int lr = lane >> 2, lc = lane & 3;
    const int m0 = blockIdx.x * BM;

    float c[MT][NT][4];
#pragma unroll
    for (int mt = 0; mt < MT; mt++)
#pragma unroll
        for (int nt = 0; nt < NT; nt++)
#pragma unroll
            for (int q = 0; q < 4; q++) c[mt][nt][q] = 0.0f;

    auto load_stage = [&](int s, int kt) {
        const int kk = kt * 32;
        float* dA = sA + s * BM * SA;
        float* dB = sB + s * BN * SA;
#pragma unroll
        for (int i = 0; i < 4; i++) {
            int ch = tid + 256 * i, row = ch >> 3, col = (ch & 7) * 4;
            cp_async16(dA + row * SA + col, x + (size_t)(m0 + row) * IN_DIM + kk + col);
        }
#pragma unroll
        for (int i = 0; i < 2; i++) {
            int ch = tid + 256 * i, row = ch >> 3, col = (ch & 7) * 4;
            cp_async16(dB + row * SA + col, la + (size_t)row * IN_DIM + kk + col);
        }
    };

    auto compute_stage = [&](int s) {
        const uint32_t* ab = reinterpret_cast<const uint32_t*>(sA + s * BM * SA + (wm * 32) * SA);
        const uint32_t* bb = reinterpret_cast<const uint32_t*>(sB + s * BN * SA + (wn * 32) * SA);
#pragma unroll
        for (int ks = 0; ks < 4; ks++) {
            uint32_t af[MT][4], bf[NT][2];
#pragma unroll
            for (int mt = 0; mt < MT; mt++) {
                const uint32_t* p = ab + (mt * 16 + lr) * SA + ks * 8 + lc;
                af[mt][0] = p[0]; af[mt][1] = p[8 * SA];
                af[mt][2] = p[4]; af[mt][3] = p[8 * SA + 4];
#pragma unroll
                for (int j = 0; j < 4; j++)
                    af[mt][j] = __float_as_uint(rna_tf32(__uint_as_float(af[mt][j])));
            }
#pragma unroll
            for (int nt = 0; nt < NT; nt++) {
                const uint32_t* p = bb + (nt * 8 + lr) * SA + ks * 8 + lc;
                bf[nt][0] = __float_as_uint(rna_tf32(__uint_as_float(p[0])));
                bf[nt][1] = __float_as_uint(rna_tf32(__uint_as_float(p[4])));
            }
#pragma unroll
            for (int mt = 0; mt < MT; mt++)
#pragma unroll
                for (int nt = 0; nt < NT; nt++) mma_tf32(c[mt][nt], af[mt], bf[nt]);
        }
    };

    load_stage(0, 0); cp_commit();
    load_stage(1, 1); cp_commit();
    cp_wait<1>();
    __syncthreads();

    const int nk = IN_DIM / 32;                   // 128
    for (int kt = 0; kt < nk; kt++) {
        int ls = kt + 2;
        if (ls < nk) load_stage(ls % STAGES, ls);
        cp_commit();
        compute_stage(kt % STAGES);
        cp_wait<1>();
        __syncthreads();
    }

    // Epilogue: rna(2*acc) -> g_X[:, 4096 + permpos(col)]
#pragma unroll
    for (int mt = 0; mt < MT; mt++) {
        int r0 = m0 + wm * 32 + mt * 16 + lr;
#pragma unroll
        for (int nt = 0; nt < NT; nt++) {
            int cc = wn * 32 + nt * 8 + 2 * lc;
            int p0 = IN_DIM + (cc & ~7) + perm8(cc & 7);
            int p1 = IN_DIM + ((cc + 1) & ~7) + perm8((cc + 1) & 7);
            g_X[(size_t)r0 * KX + p0]       = rna_tf32(2.0f * c[mt][nt][0]);
            g_X[(size_t)r0 * KX + p1]       = rna_tf32(2.0f * c[mt][nt][1]);
            g_X[(size_t)(r0 + 8) * KX + p0] = rna_tf32(2.0f * c[mt][nt][2]);
            g_X[(size_t)(r0 + 8) * KX + p1] = rna_tf32(2.0f * c[mt][nt][3]);
        }
    }
}

// ---------------------------------------------------------------------------
// Launch 2: prep (permuted writes everywhere)
//   blocks [0,1024)    : NF4 dequant -> g_W cols [0,4096)
//   blocks [1024,3072) : rna(x)      -> g_X cols [0,4096)
//   blocks [3072,3200) : rna(lora_B) -> g_W cols [4096,4160)
// ---------------------------------------------------------------------------
__global__ __launch_bounds__(256)
void prep(const float4* __restrict__ x4,
          const float4* __restrict__ lb4,
          const float* __restrict__ absmax,
          const int* __restrict__ codes) {
    const int b = blockIdx.x, t = threadIdx.x;
    if (b < 1024) {
        int blk = b * 256 + t;                    // nf4 block (64 values)
        float s = absmax[blk];
        const int4* c4 = reinterpret_cast<const int4*>(codes) + (size_t)blk * 16;
        float* orow = g_W + (size_t)(blk >> 6) * KX + (blk & 63) * 64;
#pragma unroll
        for (int g = 0; g < 8; g++) {
            int4 ca = c4[2 * g], cb = c4[2 * g + 1];
            float v0 = rna_tf32(c_nf4[ca.x & 15] * s);
            float v1 = rna_tf32(c_nf4[ca.y & 15] * s);
            float v2 = rna_tf32(c_nf4[ca.z & 15] * s);
            float v3 = rna_tf32(c_nf4[ca.w & 15] * s);
            float v4 = rna_tf32(c_nf4[cb.x & 15] * s);
            float v5 = rna_tf32(c_nf4[cb.y & 15] * s);
            float v6 = rna_tf32(c_nf4[cb.z & 15] * s);
            float v7 = rna_tf32(c_nf4[cb.w & 15] * s);
            float4* d = reinterpret_cast<float4*>(orow + g * 8);
            d[0] = make_float4(v0, v4, v1, v5);
            d[1] = make_float4(v2, v6, v3, v7);
        }
    } else if (b < 3072) {
        const int ngrp = M_TOTAL * IN_DIM / 8;
        for (int i = (b - 1024) * 256 + t; i < ngrp; i += 2048 * 256) {
            int m = i >> 9, g = i & 511;
            const float4* src = x4 + ((size_t)m * IN_DIM + g * 8) / 4;
            float4 a = src[0], q = src[1];
            float* dst = g_X + (size_t)m * KX + g * 8;
            float4* d = reinterpret_cast<float4*>(dst);
            d[0] = make_float4(rna_tf32(a.x), rna_tf32(q.x), rna_tf32(a.y), rna_tf32(q.y));
            d[1] = make_float4(rna_tf32(a.z), rna_tf32(q.z), rna_tf32(a.w), rna_tf32(q.w));
        }
    } else {
        int j = (b - 3072) * 256 + t;             // 32768 : lora_B 8-groups
        int n = j >> 3, g = j & 7;
        const float4* src = lb4 + ((size_t)n * 64 + g * 8) / 4;
        float4 a = src[0], q = src[1];
        float* dst = g_W + (size_t)n * KX + IN_DIM + g * 8;
        float4* d = reinterpret_cast<float4*>(dst);
        d[0] = make_float4(rna_tf32(a.x), rna_tf32(q.x), rna_tf32(a.y), rna_tf32(q.y));
        d[1] = make_float4(rna_tf32(a.z), rna_tf32(q.z), rna_tf32(a.w), rna_tf32(q.w));
    }
}

// ---------------------------------------------------------------------------
// Launch 3: main tf32 GEMM  out = [x|T] @ [W|loraB]^T   (K = 4160)
//   CTA 128x128, 128 threads, 4 warps (2x2) of 64x64, BK=32, 3 stages,
//   2 CTAs/SM.  Pair-permuted K layout -> all fragment loads are LDS.64.
// ---------------------------------------------------------------------------
__global__ __launch_bounds__(128, 2)
void gemm_main(float* __restrict__ out) {
    constexpr int BM = 128, BN = 128, SA = 36, STAGES = 3;
    constexpr int MT = 4, NT = 8;                 // warp tile 64x64
    constexpr int GROUP = 8, NBLK = OUT_DIM / BN;

    float* smem = reinterpret_cast<float*>(smem_raw);
    float* sA = smem;
    float* sB = smem + STAGES * BM * SA;

    const int tid = threadIdx.x, lane = tid & 31, wid = tid >> 5;
    const int wm = wid & 1, wn = wid >> 1;        // 2x2 warps
    const int lr = lane >> 2, lc = lane & 3;

    const int bid = blockIdx.x;
    const int grp = bid / (GROUP * NBLK);
    const int rem = bid % (GROUP * NBLK);
    const int m0 = (grp * GROUP + rem % GROUP) * BM;
    const int n0 = (rem / GROUP) * BN;

    const float* gA = g_X + (size_t)m0 * KX;
    const float* gB = g_W + (size_t)n0 * KX;

    float c[MT][NT][4];
#pragma unroll
    for (int mt = 0; mt < MT; mt++)
#pragma unroll
        for (int nt = 0; nt < NT; nt++)
#pragma unroll
            for (int q = 0; q < 4; q++) c[mt][nt][q] = 0.0f;

    auto load_stage = [&](int s, int kt) {
        const int kk = kt * 32;
        float* dA = sA + s * BM * SA;
        float* dB = sB + s * BN * SA;
#pragma unroll
        for (int i = 0; i < 8; i++) {             // A: 1024 chunks / 128 thr
            int ch = tid + 128 * i, row = ch >> 3, col = (ch & 7) * 4;
            cp_async16(dA + row * SA + col, gA + (size_t)row * KX + kk + col);
        }
#pragma unroll
        for (int i = 0; i < 8; i++) {             // B: 1024 chunks
            int ch = tid + 128 * i, row = ch >> 3, col = (ch & 7) * 4;
            cp_async16(dB + row * SA + col, gB + (size_t)row * KX + kk + col);
        }
    };

    auto compute_stage = [&](int s) {
        const float* aw = sA + s * BM * SA + (wm * 64) * SA;
        const float* bw = sB + s * BN * SA + (wn * 64) * SA;
#pragma unroll
        for (int ks = 0; ks < 4; ks++) {
            uint32_t af[MT][4], bf[NT][2];
#pragma unroll
            for (int mt = 0; mt < MT; mt++) {
                uint2 lo = *reinterpret_cast<const uint2*>(aw + (mt * 16 + lr) * SA + ks * 8 + 2 * lc);
                uint2 hi = *reinterpret_cast<const uint2*>(aw + (mt * 16 + lr + 8) * SA + ks * 8 + 2 * lc);
                af[mt][0] = lo.x; af[mt][2] = lo.y;   // k=lc, k=lc+4 (permuted pair)
                af[mt][1] = hi.x; af[mt][3] = hi.y;
            }
#pragma unroll
            for (int nt = 0; nt < NT; nt++) {
                uint2 bb = *reinterpret_cast<const uint2*>(bw + (nt * 8 + lr) * SA + ks * 8 + 2 * lc);
                bf[nt][0] = bb.x; bf[nt][1] = bb.y;
            }
#pragma unroll
            for (int mt = 0; mt < MT; mt++)
#pragma unroll
                for (int nt = 0; nt < NT; nt++) mma_tf32(c[mt][nt], af[mt], bf[nt]);
        }
    };

    load_stage(0, 0); cp_commit();
    load_stage(1, 1); cp_commit();
    cp_wait<1>();
    __syncthreads();

    const int nk = KX / 32;                       // 130
    for (int kt = 0; kt < nk; kt++) {
        int ls = kt + 2;
        if (ls < nk) load_stage(ls % STAGES, ls);
        cp_commit();
        compute_stage(kt % STAGES);
        cp_wait<1>();
        __syncthreads();
    }

    // Epilogue (out is plain row-major, no permutation)
#pragma unroll
    for (int mt = 0; mt < MT; mt++) {
        int r0 = m0 + wm * 64 + mt * 16 + lr;
#pragma unroll
        for (int nt = 0; nt < NT; nt++) {
            int cc = n0 + wn * 64 + nt * 8 + 2 * lc;
            *reinterpret_cast<float2*>(&out[(size_t)r0 * OUT_DIM + cc]) =
                make_float2(c[mt][nt][0], c[mt][nt][1]);
            *reinterpret_cast<float2*>(&out[(size_t)(r0 + 8) * OUT_DIM + cc]) =
                make_float2(c[mt][nt][2], c[mt][nt][3]);
        }
    }
}

// ---------------------------------------------------------------------------
// Host
// ---------------------------------------------------------------------------
extern "C" void kernel_launch(void* const* d_in, const int* in_sizes, int n_in,
                              void* d_out, int out_size) {
    const float* x      = (const float*)d_in[0];
    const float* lora_A = (const float*)d_in[1];
    const float* lora_B = (const float*)d_in[2];
    const float* absmax = (const float*)d_in[3];
    const int*   codes  = (const int*)d_in[4];
    float* out = (float*)d_out;

    constexpr int SMEM_TG   = 3 * (128 + 64) * 36 * 4;    //  82944
    constexpr int SMEM_MAIN = 3 * (128 + 128) * 36 * 4;   // 110592 -> 2 CTA/SM
    static bool attr_done = false;
    if (!attr_done) {
        cudaFuncSetAttribute((const void*)gemm_T,
                             cudaFuncAttributeMaxDynamicSharedMemorySize, SMEM_TG);
        cudaFuncSetAttribute((const void*)gemm_main,
                             cudaFuncAttributeMaxDynamicSharedMemorySize, SMEM_MAIN);
        attr_done = true;
    }

    // 1) T = rna(2 * x @ lora_A^T) -> g_X cols 4096.. (permuted)
    gemm_T<<<M_TOTAL / 128, 256, SMEM_TG>>>(x, lora_A);

    // 2) dequant W + round x + round lora_B (all permuted K layout)
    prep<<<3200, 256>>>((const float4*)x, (const float4*)lora_B, absmax, codes);

    // 3) out = [x|T] @ [W|loraB]^T
    gemm_main<<<(M_TOTAL / 128) * (OUT_DIM / 128), 128, SMEM_MAIN>>>(out);
}

// round 8
// speedup vs baseline: 3.4465x; 1.0593x over previous
#include <cuda_runtime.h>
#include <cstdint>

// ---------------------------------------------------------------------------
// Problem constants
// ---------------------------------------------------------------------------
#define OUT_DIM 4096
#define IN_DIM  4096
#define M_TOTAL 8192                 // 4 * 2048
#define R_DIM   64

// W' = rna_tf32( dequant_nf4(W) + 2 * lora_B @ lora_A )   [4096][4096]
__device__ float g_W[(size_t)OUT_DIM * IN_DIM];

__constant__ float c_nf4[16] = {
    -1.0f, -0.6961928009986877f, -0.5250730514526367f, -0.39491748809814453f,
    -0.28444138169288635f, -0.18477343022823334f, -0.09105003625154495f, 0.0f,
    0.07958029955625534f, 0.16093020141124725f, 0.24611230194568634f, 0.33791524171829224f,
    0.44070982933044434f, 0.5626170039176941f, 0.7229568362236023f, 1.0f};

// ---------------------------------------------------------------------------
// Helpers
// ---------------------------------------------------------------------------
__device__ __forceinline__ float rna_tf32(float v) {
    uint32_t r;
    asm("cvt.rna.tf32.f32 %0, %1;" : "=r"(r) : "f"(v));
    return __uint_as_float(r);
}

__device__ __forceinline__ void cp_async16(void* smem_dst, const void* gptr) {
    uint32_t s = (uint32_t)__cvta_generic_to_shared(smem_dst);
    asm volatile("cp.async.cg.shared.global [%0], [%1], 16;" :: "r"(s), "l"(gptr));
}
__device__ __forceinline__ void cp_commit() {
    asm volatile("cp.async.commit_group;" ::: "memory");
}
template <int N>
__device__ __forceinline__ void cp_wait() {
    asm volatile("cp.async.wait_group %0;" :: "n"(N) : "memory");
}

// tf32: D += A(16x8) * B(8x8)
__device__ __forceinline__ void mma_tf32(float* c, const uint32_t* a, const uint32_t* b) {
    asm volatile(
        "mma.sync.aligned.m16n8k8.row.col.f32.tf32.tf32.f32 "
        "{%0,%1,%2,%3}, {%4,%5,%6,%7}, {%8,%9}, {%0,%1,%2,%3};"
        : "+f"(c[0]), "+f"(c[1]), "+f"(c[2]), "+f"(c[3])
        : "r"(a[0]), "r"(a[1]), "r"(a[2]), "r"(a[3]), "r"(b[0]), "r"(b[1]));
}

extern __shared__ char smem_raw[];

// ---------------------------------------------------------------------------
// Launch 1: prep_w — W'[n][k] = rna( nf4[code]*absmax + 2 * sum_r B[n][r]*A[r][k] )
//   CTA computes a 128(n) x 128(k) tile. SIMT FFMA rank-64 update fused with
//   NF4 dequant. 256 threads as 16x16, each thread an 8x8 register tile.
// ---------------------------------------------------------------------------
__global__ __launch_bounds__(256)
void prep_w(const float* __restrict__ lora_A,   // [64][4096]
            const float* __restrict__ lora_B,   // [4096][64]
            const float* __restrict__ absmax,   // [262144]
            const int*   __restrict__ codes) {  // [4096][4096]
    constexpr int PAD = 132;
    float* sBt = reinterpret_cast<float*>(smem_raw);  // [64][132] : B^T (r, n_local)
    float* sA  = sBt + 64 * PAD;                      // [64][132] : A   (r, k_local)

    const int tid = threadIdx.x;
    const int n0 = blockIdx.y * 128, k0 = blockIdx.x * 128;

    // Load B tile transposed: sBt[r][row] = lora_B[n0+row][r]
    for (int idx = tid; idx < 128 * 16; idx += 256) {
        int row = idx & 127, rq = idx >> 7;           // rq in [0,16): 4 r's each
        float4 v = *reinterpret_cast<const float4*>(&lora_B[(size_t)(n0 + row) * R_DIM + rq * 4]);
        sBt[(rq * 4 + 0) * PAD + row] = v.x;
        sBt[(rq * 4 + 1) * PAD + row] = v.y;
        sBt[(rq * 4 + 2) * PAD + row] = v.z;
        sBt[(rq * 4 + 3) * PAD + row] = v.w;
    }
    // Load A tile: sA[r][c] = lora_A[r][k0+c]
    for (int idx = tid; idx < 64 * 32; idx += 256) {
        int r = idx >> 5, c4 = idx & 31;
        *reinterpret_cast<float4*>(&sA[r * PAD + c4 * 4]) =
            *reinterpret_cast<const float4*>(&lora_A[(size_t)r * IN_DIM + k0 + c4 * 4]);
    }
    __syncthreads();

    const int ty = tid >> 4, tx = tid & 15;           // 16 x 16 thread grid
    float acc[8][8];
#pragma unroll
    for (int i = 0; i < 8; i++)
#pragma unroll
        for (int j = 0; j < 8; j++) acc[i][j] = 0.0f;

    for (int r = 0; r < R_DIM; r++) {
        float bv[8], av[8];
        float4 b0 = *reinterpret_cast<const float4*>(&sBt[r * PAD + ty * 8]);
        float4 b1 = *reinterpret_cast<const float4*>(&sBt[r * PAD + ty * 8 + 4]);
        float4 a0 = *reinterpret_cast<const float4*>(&sA[r * PAD + tx * 8]);
        float4 a1 = *reinterpret_cast<const float4*>(&sA[r * PAD + tx * 8 + 4]);
        bv[0] = b0.x; bv[1] = b0.y; bv[2] = b0.z; bv[3] = b0.w;
        bv[4] = b1.x; bv[5] = b1.y; bv[6] = b1.z; bv[7] = b1.w;
        av[0] = a0.x; av[1] = a0.y; av[2] = a0.z; av[3] = a0.w;
        av[4] = a1.x; av[5] = a1.y; av[6] = a1.z; av[7] = a1.w;
#pragma unroll
        for (int i = 0; i < 8; i++)
#pragma unroll
            for (int j = 0; j < 8; j++) acc[i][j] = fmaf(bv[i], av[j], acc[i][j]);
    }

    // Combine with NF4 dequant, rna, write W'
#pragma unroll
    for (int i = 0; i < 8; i++) {
        int n = n0 + ty * 8 + i;
        int k = k0 + tx * 8;                          // 8-chunk never crosses a 64-block
        float am = absmax[n * 64 + (k >> 6)];
        const int4* cp = reinterpret_cast<const int4*>(&codes[(size_t)n * IN_DIM + k]);
        int4 c0 = cp[0], c1 = cp[1];
        float4 o0, o1;
        o0.x = rna_tf32(fmaf(c_nf4[c0.x & 15], am, 2.0f * acc[i][0]));
        o0.y = rna_tf32(fmaf(c_nf4[c0.y & 15], am, 2.0f * acc[i][1]));
        o0.z = rna_tf32(fmaf(c_nf4[c0.z & 15], am, 2.0f * acc[i][2]));
        o0.w = rna_tf32(fmaf(c_nf4[c0.w & 15], am, 2.0f * acc[i][3]));
        o1.x = rna_tf32(fmaf(c_nf4[c1.x & 15], am, 2.0f * acc[i][4]));
        o1.y = rna_tf32(fmaf(c_nf4[c1.y & 15], am, 2.0f * acc[i][5]));
        o1.z = rna_tf32(fmaf(c_nf4[c1.z & 15], am, 2.0f * acc[i][6]));
        o1.w = rna_tf32(fmaf(c_nf4[c1.w & 15], am, 2.0f * acc[i][7]));
        float4* op = reinterpret_cast<float4*>(&g_W[(size_t)n * IN_DIM + k]);
        op[0] = o0;
        op[1] = o1;
    }
}

// ---------------------------------------------------------------------------
// Launch 2: main tf32 GEMM  out = x @ W'^T   (K = 4096)
//   Proven R4 shape: CTA 128x128, 256 thr, warps 2(m)x4(n) of 64x32,
//   BK=32, 3 stages cp.async, 2 CTAs/SM, GROUP=8 swizzle, SA=36 pad.
//   A (x) read raw from input; rna applied to A fragments in registers.
//   B (W') pre-rounded in prep_w.
// ---------------------------------------------------------------------------
__global__ __launch_bounds__(256, 2)
void gemm_main(const float* __restrict__ x, float* __restrict__ out) {
    constexpr int BM = 128, BN = 128, SA = 36, STAGES = 3;
    constexpr int MT = 4, NT = 4;                 // warp tile 64x32
    constexpr int GROUP = 8, NBLK = OUT_DIM / BN; // 32

    float* smem = reinterpret_cast<float*>(smem_raw);
    float* sA = smem;                             // [3][128*36]
    float* sB = smem + STAGES * BM * SA;          // [3][128*36]

    const int tid = threadIdx.x, lane = tid & 31, wid = tid >> 5;
    const int wm = wid & 1, wn = wid >> 1;        // 2 x 4 warps
    const int lr = lane >> 2, lc = lane & 3;

    const int bid = blockIdx.x;
    const int grp = bid / (GROUP * NBLK);
    const int rem = bid % (GROUP * NBLK);
    const int m0 = (grp * GROUP + rem % GROUP) * BM;
    const int n0 = (rem / GROUP) * BN;

    const float* gA = x + (size_t)m0 * IN_DIM;
    const float* gB = g_W + (size_t)n0 * IN_DIM;

    float c[MT][NT][4];
#pragma unroll
    for (int mt = 0; mt < MT; mt++)
#pragma unroll
        for (int nt = 0; nt < NT; nt++)
#pragma unroll
            for (int q = 0; q < 4; q++) c[mt][nt][q] = 0.0f;

    auto load_stage = [&](int s, int kt) {
        const int kk = kt * 32;
        float* dA = sA + s * BM * SA;
        float* dB = sB + s * BN * SA;
#pragma unroll
        for (int i = 0; i < 4; i++) {             // A: 1024 chunks / 256 thr
            int ch = tid + 256 * i, row = ch >> 3, col = (ch & 7) * 4;
            cp_async16(dA + row * SA + col, gA + (size_t)row * IN_DIM + kk + col);
        }
#pragma unroll
        for (int i = 0; i < 4; i++) {             // B: 1024 chunks
            int ch = tid + 256 * i, row = ch >> 3, col = (ch & 7) * 4;
            cp_async16(dB + row * SA + col, gB + (size_t)row * IN_DIM + kk + col);
        }
    };

    auto compute_stage = [&](int s) {
        const uint32_t* ab = reinterpret_cast<const uint32_t*>(sA + s * BM * SA + (wm * 64) * SA);
        const uint32_t* bb = reinterpret_cast<const uint32_t*>(sB + s * BN * SA + (wn * 32) * SA);
#pragma unroll
        for (int ks = 0; ks < 4; ks++) {
            uint32_t af[MT][4], bf[NT][2];
#pragma unroll
            for (int mt = 0; mt < MT; mt++) {
                const uint32_t* p = ab + (mt * 16 + lr) * SA + ks * 8 + lc;
                af[mt][0] = p[0];
                af[mt][1] = p[8 * SA];
                af[mt][2] = p[4];
                af[mt][3] = p[8 * SA + 4];
                // x is raw fp32: round fragments to tf32 (rna) in registers
#pragma unroll
                for (int j = 0; j < 4; j++)
                    af[mt][j] = __float_as_uint(rna_tf32(__uint_as_float(af[mt][j])));
            }
#pragma unroll
            for (int nt = 0; nt < NT; nt++) {
                const uint32_t* p = bb + (nt * 8 + lr) * SA + ks * 8 + lc;
                bf[nt][0] = p[0];                 // W' already tf32-rounded
                bf[nt][1] = p[4];
            }
#pragma unroll
            for (int mt = 0; mt < MT; mt++)
#pragma unroll
                for (int nt = 0; nt < NT; nt++) mma_tf32(c[mt][nt], af[mt], bf[nt]);
        }
    };

    load_stage(0, 0); cp_commit();
    load_stage(1, 1); cp_commit();
    cp_wait<1>();
    __syncthreads();

    const int nk = IN_DIM / 32;                   // 128
    for (int kt = 0; kt < nk; kt++) {
        int ls = kt + 2;
        if (ls < nk) load_stage(ls % STAGES, ls);
        cp_commit();
        compute_stage(kt % STAGES);
        cp_wait<1>();
        __syncthreads();
    }

    // Epilogue
#pragma unroll
    for (int mt = 0; mt < MT; mt++) {
        int r0 = m0 + wm * 64 + mt * 16 + lr;
#pragma unroll
        for (int nt = 0; nt < NT; nt++) {
            int cc = n0 + wn * 32 + nt * 8 + 2 * lc;
            *reinterpret_cast<float2*>(&out[(size_t)r0 * OUT_DIM + cc]) =
                make_float2(c[mt][nt][0], c[mt][nt][1]);
            *reinterpret_cast<float2*>(&out[(size_t)(r0 + 8) * OUT_DIM + cc]) =
                make_float2(c[mt][nt][2], c[mt][nt][3]);
        }
    }
}

// ---------------------------------------------------------------------------
// Host
// ---------------------------------------------------------------------------
extern "C" void kernel_launch(void* const* d_in, const int* in_sizes, int n_in,
                              void* d_out, int out_size) {
    const float* x      = (const float*)d_in[0];
    const float* lora_A = (const float*)d_in[1];
    const float* lora_B = (const float*)d_in[2];
    const float* absmax = (const float*)d_in[3];
    const int*   codes  = (const int*)d_in[4];
    float* out = (float*)d_out;

    constexpr int SMEM_PREP = 2 * 64 * 132 * 4;          //  67584
    constexpr int SMEM_MAIN = 3 * (128 + 128) * 36 * 4;  // 110592 -> 2 CTA/SM
    static bool attr_done = false;
    if (!attr_done) {
        cudaFuncSetAttribute((const void*)prep_w,
                             cudaFuncAttributeMaxDynamicSharedMemorySize, SMEM_PREP);
        cudaFuncSetAttribute((const void*)gemm_main,
                             cudaFuncAttributeMaxDynamicSharedMemorySize, SMEM_MAIN);
        attr_done = true;
    }

    // 1) W' = rna(dequant_nf4(W) + 2 * lora_B @ lora_A)
    prep_w<<<dim3(IN_DIM / 128, OUT_DIM / 128), 256, SMEM_PREP>>>(
        lora_A, lora_B, absmax, codes);

    // 2) out = x @ W'^T
    gemm_main<<<(M_TOTAL / 128) * (OUT_DIM / 128), 256, SMEM_MAIN>>>(x, out);
}